// round 6
// baseline (speedup 1.0000x reference)
#include <cuda_runtime.h>
#include <cstdint>

// ---------------- problem constants ----------------
#define EN_V   10000
#define DE_V   19000
#define EMB_E  64
#define EMB_D  32
#define HID    32
#define G4     128          // 4*H gate rows
#define BB     64           // batch
#define S_EN   50
#define S_DE   50
#define NSTEP  (S_DE - 1)   // 49 decoder steps

// persistent grid config
#define NBLK    148
#define GROUPS  4
#define CHUNKS  37          // GROUPS*CHUNKS == NBLK
#define BPG     16          // batches per group
#define RPC     514         // rows per chunk: 37*514 = 19018 >= 19000

// phase-A block ranges
#define NEBLK   84          // blocks 0..83: E precompute (84*256 >= 19000)
#define ENCBLK0 84          // blocks 84..147: encoder (lower 128 thr) + zero/prefetch (upper 128 thr)

typedef unsigned long long u64;

// ---------------- device scratch (no allocs allowed) ----------------
__device__ float g_h[2][BB][HID];
__device__ float g_c[2][BB][HID];
__device__ float g_E[DE_V][G4];              // de_emb @ dec_Wih.T + bih + bhh (~9.7MB)
__device__ u64   g_amax[NSTEP][BB];          // packed (key<<32)|~idx argmax per step
// global barrier (phase A -> decode)
__device__ unsigned          g_bar_count;
__device__ volatile unsigned g_bar_gen;
// per-(group,step) completion counters: no reset, no release round needed.
// 64 words (256B) per group so groups never share a 128B line.
__device__ unsigned g_done[GROUPS][64];

// ---------------- helpers ----------------
__device__ __forceinline__ float sigf(float x) { return 1.0f / (1.0f + expf(-x)); }
__device__ __forceinline__ float tanh_acc(float x) {
    float ax = fabsf(x);
    float e  = expf(-2.0f * ax);
    float r  = (1.0f - e) / (1.0f + e);
    return (x < 0.0f) ? -r : r;
}
__device__ __forceinline__ u64 fma2(u64 a, u64 b, u64 c) {
    u64 d;
    asm("fma.rn.f32x2 %0, %1, %2, %3;" : "=l"(d) : "l"(a), "l"(b), "l"(c));
    return d;
}
__device__ __forceinline__ float lo32(u64 v) { return __uint_as_float((unsigned)v); }
__device__ __forceinline__ float hi32(u64 v) { return __uint_as_float((unsigned)(v >> 32)); }
// order-preserving float->uint key (larger key <=> larger float)
__device__ __forceinline__ unsigned key_of(float f) {
    unsigned u = __float_as_uint(f);
    return (u & 0x80000000u) ? ~u : (u | 0x80000000u);
}
__device__ __forceinline__ void bar_enc() {     // named barrier, encoder half only
    asm volatile("bar.sync 1, 128;" ::: "memory");
}
__device__ __forceinline__ void l2_prefetch(const void* p) {
    asm volatile("prefetch.global.L2 [%0];" :: "l"(p));
}

// global software barrier (all NBLK blocks co-resident: grid <= #SM, 1 CTA/SM)
__device__ __forceinline__ void grid_sync() {
    __syncthreads();
    if (threadIdx.x == 0) {
        unsigned gen = g_bar_gen;            // read BEFORE arriving
        __threadfence();                     // release my block's prior writes
        unsigned prev = atomicAdd(&g_bar_count, 1u);
        if (prev == gridDim.x - 1) {
            atomicExch(&g_bar_count, 0u);
            __threadfence();
            g_bar_gen = gen + 1;             // release everyone
        } else {
            while (g_bar_gen == gen) { }     // volatile L2 spin
            __threadfence();                 // acquire
        }
    }
    __syncthreads();
}

// ---------------- the persistent kernel ----------------
__global__ void __launch_bounds__(256, 1) seq2seq_kernel(
    const int*   __restrict__ en_batch,
    const int*   __restrict__ en_lens,
    const int*   __restrict__ de_batch,
    const float* __restrict__ en_emb,
    const float* __restrict__ enc_Wih,
    const float* __restrict__ enc_Whh,
    const float* __restrict__ enc_bih,
    const float* __restrict__ enc_bhh,
    const float* __restrict__ de_emb,
    const float* __restrict__ dec_Wih,
    const float* __restrict__ dec_bih,
    const float* __restrict__ dec_bhh,
    const float* __restrict__ dec_Whh,
    const float* __restrict__ fc_W,
    const float* __restrict__ fc_b,
    float*       __restrict__ out)
{
    __shared__ __align__(16) unsigned char sraw[35072];
    const int blk = blockIdx.x;
    const int tid = threadIdx.x;

    // ================= PHASE A =================
    if (blk < NEBLK) {
        // ---- E = de_emb @ dec_Wih.T + bih + bhh : one vocab row per thread ----
        float* Ws    = (float*)sraw;                  // [G4*HID] 16KB
        float* biasS = (float*)(sraw + G4 * HID * 4); // [G4]
        for (int i = tid; i < G4 * HID; i += 256) Ws[i] = dec_Wih[i];
        if (tid < G4) biasS[tid] = dec_bih[tid] + dec_bhh[tid];
        __syncthreads();
        int v = blk * 256 + tid;
        if (v < DE_V) {
            const u64* xr = (const u64*)(de_emb + (size_t)v * HID);
            u64 x2[16];
#pragma unroll
            for (int k = 0; k < 16; k++) x2[k] = xr[k];
            const u64* W2 = (const u64*)Ws;
            float* Erow = &g_E[v][0];
            for (int g = 0; g < G4; g += 4) {
                float4 r;
                float* rp = (float*)&r;
#pragma unroll
                for (int gg = 0; gg < 4; gg++) {
                    u64 acc = 0ull;
                    const u64* w = W2 + (size_t)(g + gg) * 16;
#pragma unroll
                    for (int k = 0; k < 16; k++) acc = fma2(w[k], x2[k], acc);
                    rp[gg] = lo32(acc) + hi32(acc) + biasS[g + gg];
                }
                *(float4*)(Erow + g) = r;
            }
        }
    } else if (tid < 128) {
        // ---- encoder: one batch element per block, lower 128 threads ----
        const int b = blk - ENCBLK0;
        int*   tokS = (int*)sraw;                       // [S_EN]
        float* xs   = (float*)(sraw + 256);             // [2][EMB_E]
        float* hs   = (float*)(sraw + 256 + 512);       // [HID]
        float* cs   = (float*)(sraw + 256 + 640);       // [HID]
        float* egs  = (float*)(sraw + 256 + 768);       // [G4]
        if (tid < HID) { hs[tid] = 0.f; cs[tid] = 0.f; }
        if (tid < S_EN) tokS[tid] = en_batch[b * S_EN + tid];
        const int len = en_lens[b];
        const float bias = enc_bih[tid] + enc_bhh[tid];
        float wx[EMB_E], wh[HID];
#pragma unroll
        for (int k = 0; k < EMB_E; k++) wx[k] = enc_Wih[tid * EMB_E + k];
#pragma unroll
        for (int k = 0; k < HID; k++)   wh[k] = enc_Whh[tid * HID + k];
        bar_enc();
        // preload x(0)
        if (tid < EMB_E) xs[tid] = en_emb[(size_t)tokS[0] * EMB_E + tid];
        bar_enc();

        for (int t = 0; t < len; t++) {
            const float* xcur = xs + (t & 1) * EMB_E;
            // prefetch x(t+1) while gates compute (tokens are inputs, known ahead)
            float xreg = 0.f;
            if (tid < EMB_E && t + 1 < len)
                xreg = en_emb[(size_t)tokS[t + 1] * EMB_E + tid];
            float a0 = bias, a1 = 0.f, a2 = 0.f, a3 = 0.f;
#pragma unroll
            for (int k = 0; k < EMB_E; k += 4) {
                a0 += wx[k] * xcur[k];         a1 += wx[k + 1] * xcur[k + 1];
                a2 += wx[k + 2] * xcur[k + 2]; a3 += wx[k + 3] * xcur[k + 3];
            }
#pragma unroll
            for (int k = 0; k < HID; k += 4) {
                a0 += wh[k] * hs[k];         a1 += wh[k + 1] * hs[k + 1];
                a2 += wh[k + 2] * hs[k + 2]; a3 += wh[k + 3] * hs[k + 3];
            }
            egs[tid] = (a0 + a1) + (a2 + a3);
            bar_enc();
            if (tid < HID) {
                float i_ = sigf(egs[tid]);
                float f_ = sigf(egs[tid + 32]);
                float gg = tanh_acc(egs[tid + 64]);
                float o_ = sigf(egs[tid + 96]);
                float cn = f_ * cs[tid] + i_ * gg;
                cs[tid] = cn;
                hs[tid] = o_ * tanh_acc(cn);
            }
            if (tid < EMB_E && t + 1 < len)
                xs[((t + 1) & 1) * EMB_E + tid] = xreg;
            bar_enc();
        }
        if (tid < HID) {
            __stcg(&g_h[0][b][tid], hs[tid]);
            __stcg(&g_c[0][b][tid], cs[tid]);
        }
    } else {
        // ---- upper 128 threads of encoder blocks: zeroing + L2 warm of fc_W ----
        int z = (blk - ENCBLK0) * 128 + (tid - 128);   // 0..8191
        u64* am = (u64*)g_amax;
        for (int i = z; i < NSTEP * BB; i += 64 * 128) __stcg(&am[i], 0ull);
        unsigned* dn = (unsigned*)g_done;
        if (z < GROUPS * 64) __stcg(&dn[z], 0u);       // re-zero step counters (replay)
        const int total4 = (BB * DE_V) / 4;            // 304000
        float4 zf = make_float4(0.f, 0.f, 0.f, 0.f);
        for (int j = z; j < total4; j += 64 * 128) {
            int e = j * 4;                             // DE_V % 4 == 0
            int b = e / DE_V;
            int r = e - b * DE_V;
            *(float4*)(out + (size_t)b * S_DE * DE_V + r) = zf;
        }
        // warm L2 with fc_W (2.43 MB) + fc_b so decode step 0 avoids cold DRAM
        {
            const int lines = (DE_V * HID * 4) / 128;  // 19000 lines
            for (int i = z; i < lines; i += 64 * 128)
                l2_prefetch((const char*)fc_W + (size_t)i * 128);
            const int blines = (DE_V * 4 + 127) / 128; // 594 lines
            for (int i = z; i < blines; i += 64 * 128)
                l2_prefetch((const char*)fc_b + (size_t)i * 128);
        }
    }

    grid_sync();   // phase A complete everywhere (global barrier)

    // ================= DECODE: 49 steps =================
    const int group = blk / CHUNKS;     // 0..3  (groups are fully independent)
    const int chunk = blk % CHUNKS;     // 0..36
    const int b0    = group * BPG;

    // decode shared views (tail region reused: LSTM{hp,gs} then argmax{red})
    float (*hn)[HID] = (float(*)[HID])sraw;                       // 2048
    int*  toks       = (int*)(sraw + 2048);                       // 64
    float (*hp)[HID] = (float(*)[HID])(sraw + 2176);              // 2048
    float (*gs)[G4]  = (float(*)[G4]) (sraw + 2176 + 2048);       // 8192
    u64  (*red)[256] = (u64(*)[256])  (sraw + 2176);              // 32768 (overlaps hp/gs)

    for (int step = 0; step < NSTEP; step++) {
        // --- wait: all 37 blocks of this group finished step-1 (finalizes
        //     g_amax[step-1] and chunk0's g_h/g_c writes). done-counter spin:
        //     no release round, no reset, arrival is a single atomicAdd. ---
        if (step) {
            if (tid == 0) {
                volatile unsigned* dp = &g_done[group][step - 1];
                while (*dp < CHUNKS) { }
                __threadfence();               // acquire
            }
            __syncthreads();
        }
        const int rb = step & 1;
        const int wb = rb ^ 1;

        // --- tokens + previous h ---
        if (tid < BPG) {
            int b = b0 + tid;
            int tok;
            if (step == 0) tok = __ldg(&de_batch[b * S_DE]);
            else           tok = (int)(~(unsigned)__ldcg(&g_amax[step - 1][b]));
            toks[tid] = tok;
        }
#pragma unroll
        for (int u = 0; u < 2; u++) {
            int idx = tid + 256 * u;             // 512 items
            int bi = idx >> 5, j = idx & 31;
            hp[bi][j] = __ldcg(&g_h[rb][b0 + bi][j]);
        }
        __syncthreads();

        // --- gates: thread = (batch bi, gate octet q) ---
        {
            int bi = tid >> 4;
            int q  = tid & 15;
            const ulonglong2* h4 = (const ulonglong2*)hp[bi];
            const float* Ep = &g_E[toks[bi]][0];
#pragma unroll
            for (int gg = 0; gg < 8; gg++) {
                int g = q * 8 + gg;
                const ulonglong2* w = (const ulonglong2*)(dec_Whh + (size_t)g * HID);
                u64 acc = 0ull;
#pragma unroll
                for (int k4 = 0; k4 < 8; k4++) {
                    ulonglong2 wv = w[k4];
                    ulonglong2 hv = h4[k4];
                    acc = fma2(wv.x, hv.x, acc);
                    acc = fma2(wv.y, hv.y, acc);
                }
                gs[bi][g] = lo32(acc) + hi32(acc) + __ldg(Ep + g);
            }
        }
        __syncthreads();

        // --- cell update ---
#pragma unroll
        for (int u = 0; u < 2; u++) {
            int idx = tid + 256 * u;
            int bi = idx >> 5, j = idx & 31;
            float i_ = sigf(gs[bi][j]);
            float f_ = sigf(gs[bi][j + 32]);
            float gg = tanh_acc(gs[bi][j + 64]);
            float o_ = sigf(gs[bi][j + 96]);
            float cp = __ldcg(&g_c[rb][b0 + bi][j]);
            float cn = f_ * cp + i_ * gg;
            float hv = o_ * tanh_acc(cn);
            hn[bi][j] = hv;
            if (chunk == 0) {                      // single writer per group
                __stcg(&g_h[wb][b0 + bi][j], hv);
                __stcg(&g_c[wb][b0 + bi][j], cn);
            }
        }
        __syncthreads();

        // --- FC logits: rows paired (r, r+256) to halve LDS traffic ---
        u64 best[BPG];
#pragma unroll
        for (int bi = 0; bi < BPG; bi++) best[bi] = 0ull;
        const ulonglong2* h2 = (const ulonglong2*)hn;   // [BPG*8]
        const int r0   = chunk * RPC;
        const int rend = (r0 + RPC < DE_V) ? (r0 + RPC) : DE_V;

        for (int r = r0 + tid; r < rend; r += 512) {
            const int  rB   = r + 256;
            const bool has2 = (rB < rend);
            const ulonglong2* wr0 = (const ulonglong2*)(fc_W + (size_t)r * HID);
            const ulonglong2* wr1 = (const ulonglong2*)(fc_W + (size_t)(has2 ? rB : r) * HID);
            u64 acc0[BPG], acc1[BPG];
#pragma unroll
            for (int bi = 0; bi < BPG; bi++) { acc0[bi] = 0ull; acc1[bi] = 0ull; }
#pragma unroll
            for (int k4 = 0; k4 < 8; k4++) {
                ulonglong2 wv0 = wr0[k4];
                ulonglong2 wv1 = wr1[k4];
#pragma unroll
                for (int bi = 0; bi < BPG; bi++) {
                    ulonglong2 hv = h2[bi * 8 + k4];      // one LDS serves 2 rows
                    acc0[bi] = fma2(wv0.x, hv.x, acc0[bi]);
                    acc0[bi] = fma2(wv0.y, hv.y, acc0[bi]);
                    acc1[bi] = fma2(wv1.x, hv.x, acc1[bi]);
                    acc1[bi] = fma2(wv1.y, hv.y, acc1[bi]);
                }
            }
            float bias0 = __ldg(&fc_b[r]);
            float bias1 = has2 ? __ldg(&fc_b[rB]) : 0.f;
            size_t obase0 = (size_t)(step + 1) * DE_V + r;
#pragma unroll
            for (int bi = 0; bi < BPG; bi++) {
                size_t orow = (size_t)(b0 + bi) * (S_DE * DE_V);
                float logit0 = lo32(acc0[bi]) + hi32(acc0[bi]) + bias0;
                out[orow + obase0] = logit0;
                u64 p0 = ((u64)key_of(logit0) << 32) | (unsigned)(~(unsigned)r);
                if (p0 > best[bi]) best[bi] = p0;
                if (has2) {
                    float logit1 = lo32(acc1[bi]) + hi32(acc1[bi]) + bias1;
                    out[orow + obase0 + 256] = logit1;
                    u64 p1 = ((u64)key_of(logit1) << 32) | (unsigned)(~(unsigned)rB);
                    if (p1 > best[bi]) best[bi] = p1;
                }
            }
        }

        // --- block argmax reduce + one atomicMax per (block, batch) ---
#pragma unroll
        for (int bi = 0; bi < BPG; bi++) red[bi][tid] = best[bi];
        __syncthreads();
        {
            int w = tid >> 5, lane = tid & 31;
            for (int bb = w; bb < BPG; bb += 8) {
                u64 m = red[bb][lane];
#pragma unroll
                for (int off = 32; off < 256; off += 32) {
                    u64 v = red[bb][lane + off];
                    if (v > m) m = v;
                }
#pragma unroll
                for (int off = 16; off; off >>= 1) {
                    u64 v = __shfl_down_sync(0xffffffffu, m, off);
                    if (v > m) m = v;
                }
                if (lane == 0) atomicMax(&g_amax[step][b0 + bb], m);
            }
        }
        // --- arrive: this block is done with step (argmax + state writes) ---
        __syncthreads();                       // all warps' atomicMax issued
        if (tid == 0) {
            __threadfence();                   // release
            atomicAdd(&g_done[group][step], 1u);
        }
    }
}

// ---------------- launch ----------------
extern "C" void kernel_launch(void* const* d_in, const int* in_sizes, int n_in,
                              void* d_out, int out_size) {
    const int*   en_batch = (const int*)d_in[0];
    const int*   en_lens  = (const int*)d_in[1];
    const int*   de_batch = (const int*)d_in[2];
    const float* en_emb   = (const float*)d_in[3];
    const float* enc_Wih  = (const float*)d_in[4];
    const float* enc_Whh  = (const float*)d_in[5];
    const float* enc_bih  = (const float*)d_in[6];
    const float* enc_bhh  = (const float*)d_in[7];
    const float* de_emb   = (const float*)d_in[8];
    const float* dec_Wih  = (const float*)d_in[9];
    const float* dec_Whh  = (const float*)d_in[10];
    const float* dec_bih  = (const float*)d_in[11];
    const float* dec_bhh  = (const float*)d_in[12];
    const float* fc_W     = (const float*)d_in[13];
    const float* fc_b     = (const float*)d_in[14];
    float* out = (float*)d_out;

    seq2seq_kernel<<<NBLK, 256>>>(en_batch, en_lens, de_batch, en_emb,
                                  enc_Wih, enc_Whh, enc_bih, enc_bhh,
                                  de_emb, dec_Wih, dec_bih, dec_bhh, dec_Whh,
                                  fc_W, fc_b, out);
}

// round 7
// speedup vs baseline: 2.0699x; 2.0699x over previous
#include <cuda_runtime.h>
#include <cstdint>

// ---------------- problem constants ----------------
#define DE_V   19000
#define EMB_E  64
#define HID    32
#define G4     128          // 4*H gate rows
#define BB     64           // batch
#define S_EN   50
#define S_DE   50
#define NSTEP  (S_DE - 1)   // 49 decoder steps

// persistent grid config
#define NBLK    148
#define GROUPS  4
#define CHUNKS  37          // GROUPS*CHUNKS == NBLK
#define BPG     16          // batches per group
#define RPC     514         // rows per chunk: 37*514 = 19018 >= 19000

// phase-A block ranges
#define NEBLK   84          // blocks 0..83: E precompute
#define ENCBLK0 84          // blocks 84..147: encoder (lower 128 thr) + zeroing (upper)

// ---------------- dynamic smem layout ----------------
#define WHH_OFF   0                 // u64[16][128] transposed Whh pairs  = 16384
#define FCW_OFF   16384             // swizzled fc_W chunk 514*128B      = 65792
#define HP_OFF    82176             // float[16][32]                     = 2048
#define HN_OFF    84224             // float[16][32]                     = 2048
#define GS_OFF    86272             // float[16][128]                    = 8192
#define TOK_OFF   94464             // int[16] (+pad)                    = 128
#define RED_OFF   94592             // u64[16][256]                      = 32768
#define SMEM_TOTAL 127360
// phase-A aliases (overwritten by staging afterwards)
#define WS_OFF    0                 // E: dec_Wih [128*32]f = 16384
#define BIAS_OFF  16384             // E: bias [128]f
#define ENC_OFF   82176             // encoder scratch (~1.5KB)

typedef unsigned long long u64;

// ---------------- device scratch (no allocs allowed) ----------------
__device__ float g_h[2][BB][HID];
__device__ float g_c[2][BB][HID];
__device__ float g_E[DE_V][G4];              // de_emb @ dec_Wih.T + bih + bhh (~9.7MB)
__device__ u64   g_amax[NSTEP][BB];          // packed (key<<32)|~idx argmax per step
__device__ unsigned          g_bar_count;
__device__ volatile unsigned g_bar_gen;
__device__ unsigned g_done[GROUPS][64];      // per-(group,step) completion counters

// ---------------- helpers ----------------
__device__ __forceinline__ float sigf(float x) { return 1.0f / (1.0f + expf(-x)); }
__device__ __forceinline__ float tanh_acc(float x) {
    float ax = fabsf(x);
    float e  = expf(-2.0f * ax);
    float r  = (1.0f - e) / (1.0f + e);
    return (x < 0.0f) ? -r : r;
}
__device__ __forceinline__ u64 fma2(u64 a, u64 b, u64 c) {
    u64 d;
    asm("fma.rn.f32x2 %0, %1, %2, %3;" : "=l"(d) : "l"(a), "l"(b), "l"(c));
    return d;
}
__device__ __forceinline__ float lo32(u64 v) { return __uint_as_float((unsigned)v); }
__device__ __forceinline__ float hi32(u64 v) { return __uint_as_float((unsigned)(v >> 32)); }
__device__ __forceinline__ unsigned key_of(float f) {
    unsigned u = __float_as_uint(f);
    return (u & 0x80000000u) ? ~u : (u | 0x80000000u);
}
__device__ __forceinline__ void bar_enc() {
    asm volatile("bar.sync 1, 128;" ::: "memory");
}

// global software barrier (148 blocks, 1 CTA/SM, all co-resident)
__device__ __forceinline__ void grid_sync() {
    __syncthreads();
    if (threadIdx.x == 0) {
        unsigned gen = g_bar_gen;
        __threadfence();
        unsigned prev = atomicAdd(&g_bar_count, 1u);
        if (prev == gridDim.x - 1) {
            atomicExch(&g_bar_count, 0u);
            __threadfence();
            g_bar_gen = gen + 1;
        } else {
            while (g_bar_gen == gen) { }
            __threadfence();
        }
    }
    __syncthreads();
}

// ---------------- the persistent kernel ----------------
__global__ void __launch_bounds__(256, 1) seq2seq_kernel(
    const int*   __restrict__ en_batch,
    const int*   __restrict__ en_lens,
    const int*   __restrict__ de_batch,
    const float* __restrict__ en_emb,
    const float* __restrict__ enc_Wih,
    const float* __restrict__ enc_Whh,
    const float* __restrict__ enc_bih,
    const float* __restrict__ enc_bhh,
    const float* __restrict__ de_emb,
    const float* __restrict__ dec_Wih,
    const float* __restrict__ dec_bih,
    const float* __restrict__ dec_bhh,
    const float* __restrict__ dec_Whh,
    const float* __restrict__ fc_W,
    const float* __restrict__ fc_b,
    float*       __restrict__ out)
{
    extern __shared__ __align__(16) unsigned char sdyn[];
    const int blk = blockIdx.x;
    const int tid = threadIdx.x;

    // ================= PHASE A =================
    if (blk < NEBLK) {
        // ---- E = de_emb @ dec_Wih.T + bih + bhh : one vocab row per thread ----
        float* Ws    = (float*)(sdyn + WS_OFF);
        float* biasS = (float*)(sdyn + BIAS_OFF);
        for (int i = tid; i < G4 * HID; i += 256) Ws[i] = dec_Wih[i];
        if (tid < G4) biasS[tid] = dec_bih[tid] + dec_bhh[tid];
        __syncthreads();
        int v = blk * 256 + tid;
        if (v < DE_V) {
            const u64* xr = (const u64*)(de_emb + (size_t)v * HID);
            u64 x2[16];
#pragma unroll
            for (int k = 0; k < 16; k++) x2[k] = xr[k];
            const u64* W2 = (const u64*)Ws;
            float* Erow = &g_E[v][0];
            for (int g = 0; g < G4; g += 4) {
                float4 r;
                float* rp = (float*)&r;
#pragma unroll
                for (int gg = 0; gg < 4; gg++) {
                    u64 acc = 0ull;
                    const u64* w = W2 + (size_t)(g + gg) * 16;
#pragma unroll
                    for (int k = 0; k < 16; k++) acc = fma2(w[k], x2[k], acc);
                    rp[gg] = lo32(acc) + hi32(acc) + biasS[g + gg];
                }
                *(float4*)(Erow + g) = r;
            }
        }
    } else if (tid < 128) {
        // ---- encoder: one batch element per block, lower 128 threads ----
        const int b = blk - ENCBLK0;
        int*   tokS = (int*)(sdyn + ENC_OFF);            // [S_EN] (256B)
        float* xs   = (float*)(sdyn + ENC_OFF + 256);    // [2][EMB_E]
        float* hs   = (float*)(sdyn + ENC_OFF + 768);    // [HID]
        float* cs   = (float*)(sdyn + ENC_OFF + 896);    // [HID]
        float* egs  = (float*)(sdyn + ENC_OFF + 1024);   // [G4]
        if (tid < HID) { hs[tid] = 0.f; cs[tid] = 0.f; }
        if (tid < S_EN) tokS[tid] = en_batch[b * S_EN + tid];
        const int len = en_lens[b];
        const float bias = enc_bih[tid] + enc_bhh[tid];
        float wx[EMB_E], wh[HID];
#pragma unroll
        for (int k = 0; k < EMB_E; k++) wx[k] = enc_Wih[tid * EMB_E + k];
#pragma unroll
        for (int k = 0; k < HID; k++)   wh[k] = enc_Whh[tid * HID + k];
        bar_enc();
        if (tid < EMB_E) xs[tid] = en_emb[(size_t)tokS[0] * EMB_E + tid];
        bar_enc();

        for (int t = 0; t < len; t++) {
            const float* xcur = xs + (t & 1) * EMB_E;
            float xreg = 0.f;
            if (tid < EMB_E && t + 1 < len)
                xreg = en_emb[(size_t)tokS[t + 1] * EMB_E + tid];
            float a0 = bias, a1 = 0.f, a2 = 0.f, a3 = 0.f;
#pragma unroll
            for (int k = 0; k < EMB_E; k += 4) {
                a0 += wx[k] * xcur[k];         a1 += wx[k + 1] * xcur[k + 1];
                a2 += wx[k + 2] * xcur[k + 2]; a3 += wx[k + 3] * xcur[k + 3];
            }
#pragma unroll
            for (int k = 0; k < HID; k += 4) {
                a0 += wh[k] * hs[k];         a1 += wh[k + 1] * hs[k + 1];
                a2 += wh[k + 2] * hs[k + 2]; a3 += wh[k + 3] * hs[k + 3];
            }
            egs[tid] = (a0 + a1) + (a2 + a3);
            bar_enc();
            if (tid < HID) {
                float i_ = sigf(egs[tid]);
                float f_ = sigf(egs[tid + 32]);
                float gg = tanh_acc(egs[tid + 64]);
                float o_ = sigf(egs[tid + 96]);
                float cn = f_ * cs[tid] + i_ * gg;
                cs[tid] = cn;
                hs[tid] = o_ * tanh_acc(cn);
            }
            if (tid < EMB_E && t + 1 < len)
                xs[((t + 1) & 1) * EMB_E + tid] = xreg;
            bar_enc();
        }
        if (tid < HID) {
            __stcg(&g_h[0][b][tid], hs[tid]);
            __stcg(&g_c[0][b][tid], cs[tid]);
        }
    } else {
        // ---- upper 128 threads of encoder blocks: zero g_amax, g_done, out[:,0,:] ----
        int z = (blk - ENCBLK0) * 128 + (tid - 128);   // 0..8191
        u64* am = (u64*)g_amax;
        for (int i = z; i < NSTEP * BB; i += 64 * 128) __stcg(&am[i], 0ull);
        unsigned* dn = (unsigned*)g_done;
        if (z < GROUPS * 64) __stcg(&dn[z], 0u);
        const int total4 = (BB * DE_V) / 4;            // 304000
        float4 zf = make_float4(0.f, 0.f, 0.f, 0.f);
        for (int j = z; j < total4; j += 64 * 128) {
            int e = j * 4;                             // DE_V % 4 == 0
            int b = e / DE_V;
            int r = e - b * DE_V;
            *(float4*)(out + (size_t)b * S_DE * DE_V + r) = zf;
        }
    }
    __syncthreads();   // phase-A smem regions free

    // ---- stage decode operands into smem (all blocks, before grid_sync) ----
    const int group = blk / CHUNKS;     // 0..3
    const int chunk = blk % CHUNKS;     // 0..36
    const int b0    = group * BPG;
    const int r0    = chunk * RPC;
    const int nrows = (r0 + RPC < DE_V) ? RPC : (DE_V - r0);
    {
        // Whh transposed into u64 pairs: whh_p[k2*128+g] = (Whh[g][2k2], Whh[g][2k2+1])
        u64* whh = (u64*)(sdyn + WHH_OFF);
        const u64* Wg = (const u64*)dec_Whh;
        for (int i = tid; i < 16 * G4; i += 256) {
            int k2 = i >> 7, g = i & 127;
            whh[i] = Wg[(size_t)g * 16 + k2];
        }
        // fc_W chunk, XOR-swizzled 16B chunks within each 128B row
        for (int i = tid; i < nrows * 8; i += 256) {
            int rr = i >> 3, k4 = i & 7;
            ulonglong2 v = ((const ulonglong2*)(fc_W + (size_t)(r0 + rr) * HID))[k4];
            *(ulonglong2*)(sdyn + FCW_OFF + rr * 128 + ((k4 ^ (rr & 7)) << 4)) = v;
        }
    }

    grid_sync();   // phase A + staging complete everywhere

    // ================= DECODE: 49 steps =================
    float (*hp)[HID] = (float(*)[HID])(sdyn + HP_OFF);
    float (*hn)[HID] = (float(*)[HID])(sdyn + HN_OFF);
    float (*gs)[G4]  = (float(*)[G4]) (sdyn + GS_OFF);
    int*  toks       = (int*)(sdyn + TOK_OFF);
    u64  (*red)[256] = (u64(*)[256])(sdyn + RED_OFF);
    const u64* whh_p = (const u64*)(sdyn + WHH_OFF);
    const int x0   = tid & 7;           // swizzle constant (same for tid, tid+256, tid+512)
    const int rend = r0 + nrows;

    for (int step = 0; step < NSTEP; step++) {
        if (step) {      // wait: all 37 blocks of this group finished step-1
            if (tid == 0) {
                volatile unsigned* dp = &g_done[group][step - 1];
                while (*dp < CHUNKS) { }
                __threadfence();               // acquire
            }
            __syncthreads();
        }
        const int rb = step & 1;
        const int wb = rb ^ 1;

        // --- tokens + previous h ---
        if (tid < BPG) {
            int b = b0 + tid;
            int tok;
            if (step == 0) tok = __ldg(&de_batch[b * S_DE]);
            else           tok = (int)(~(unsigned)__ldcg(&g_amax[step - 1][b]));
            toks[tid] = tok;
        }
#pragma unroll
        for (int u = 0; u < 2; u++) {
            int idx = tid + 256 * u;
            hp[idx >> 5][idx & 31] = __ldcg(&g_h[rb][b0 + (idx >> 5)][idx & 31]);
        }
        __syncthreads();

        // --- gates: thread = (gate g, batch-octet). Whh row in registers. ---
        {
            const int g = tid & 127, half = tid >> 7;
            u64 wreg[16];
#pragma unroll
            for (int k2 = 0; k2 < 16; k2++) wreg[k2] = whh_p[k2 * 128 + g];
#pragma unroll
            for (int bb = 0; bb < 8; bb++) {
                int bi = half * 8 + bb;
                const ulonglong2* h4 = (const ulonglong2*)hp[bi];
                u64 acc = 0ull;
#pragma unroll
                for (int k4 = 0; k4 < 8; k4++) {
                    ulonglong2 hv = h4[k4];                 // broadcast LDS
                    acc = fma2(wreg[2 * k4],     hv.x, acc);
                    acc = fma2(wreg[2 * k4 + 1], hv.y, acc);
                }
                gs[bi][g] = lo32(acc) + hi32(acc) + __ldg(&g_E[toks[bi]][g]);
            }
        }
        __syncthreads();

        // --- cell update (512 units / 256 threads) ---
#pragma unroll
        for (int u = 0; u < 2; u++) {
            int idx = tid + 256 * u;
            int bi = idx >> 5, j = idx & 31;
            float i_ = sigf(gs[bi][j]);
            float f_ = sigf(gs[bi][j + 32]);
            float gg = tanh_acc(gs[bi][j + 64]);
            float o_ = sigf(gs[bi][j + 96]);
            float cp = __ldcg(&g_c[rb][b0 + bi][j]);
            float cn = f_ * cp + i_ * gg;
            float hv = o_ * tanh_acc(cn);
            hn[bi][j] = hv;
            if (chunk == 0) {                      // single writer per group
                __stcg(&g_h[wb][b0 + bi][j], hv);
                __stcg(&g_c[wb][b0 + bi][j], cn);
            }
        }
        __syncthreads();

        // --- FC logits from smem-staged weights, rows paired (r, r+256) ---
        unsigned bestk[BPG];
        int      bestr[BPG];
#pragma unroll
        for (int bi = 0; bi < BPG; bi++) { bestk[bi] = 0u; bestr[bi] = 0; }
        const ulonglong2* h2 = (const ulonglong2*)hn;   // [BPG*8]

        for (int r = r0 + tid; r < rend; r += 512) {
            const int  rr   = r - r0;
            const int  rB   = r + 256;
            const bool has2 = (rB < rend);
            const unsigned char* row0 = sdyn + FCW_OFF + rr * 128;
            const unsigned char* row1 = sdyn + FCW_OFF + (has2 ? (rr + 256) : rr) * 128;
            u64 acc0[BPG], acc1[BPG];
#pragma unroll
            for (int bi = 0; bi < BPG; bi++) { acc0[bi] = 0ull; acc1[bi] = 0ull; }
#pragma unroll
            for (int k4 = 0; k4 < 8; k4++) {
                const int p = ((k4 ^ x0) << 4);
                ulonglong2 wv0 = *(const ulonglong2*)(row0 + p);   // 4-wf floor (swizzled)
                ulonglong2 wv1 = *(const ulonglong2*)(row1 + p);
#pragma unroll
                for (int bi = 0; bi < BPG; bi++) {
                    ulonglong2 hv = h2[bi * 8 + k4];               // broadcast
                    acc0[bi] = fma2(wv0.x, hv.x, acc0[bi]);
                    acc0[bi] = fma2(wv0.y, hv.y, acc0[bi]);
                    acc1[bi] = fma2(wv1.x, hv.x, acc1[bi]);
                    acc1[bi] = fma2(wv1.y, hv.y, acc1[bi]);
                }
            }
            float bias0 = __ldg(&fc_b[r]);
            float bias1 = has2 ? __ldg(&fc_b[rB]) : 0.f;
            size_t obase = (size_t)(step + 1) * DE_V + r;
#pragma unroll
            for (int bi = 0; bi < BPG; bi++) {
                size_t orow = (size_t)(b0 + bi) * (S_DE * DE_V);
                float l0 = lo32(acc0[bi]) + hi32(acc0[bi]) + bias0;
                out[orow + obase] = l0;
                unsigned k0 = key_of(l0);
                if (k0 > bestk[bi]) { bestk[bi] = k0; bestr[bi] = r; }   // rows ascend: first wins
                if (has2) {
                    float l1 = lo32(acc1[bi]) + hi32(acc1[bi]) + bias1;
                    out[orow + obase + 256] = l1;
                    unsigned k1 = key_of(l1);
                    if (k1 > bestk[bi]) { bestk[bi] = k1; bestr[bi] = rB; }
                }
            }
        }

        // --- block argmax reduce + one atomicMax per (block, batch) ---
#pragma unroll
        for (int bi = 0; bi < BPG; bi++)
            red[bi][tid] = ((u64)bestk[bi] << 32) | (unsigned)(~(unsigned)bestr[bi]);
        __syncthreads();
        {
            int w = tid >> 5, lane = tid & 31;
            for (int bb = w; bb < BPG; bb += 8) {
                u64 m = red[bb][lane];
#pragma unroll
                for (int off = 32; off < 256; off += 32) {
                    u64 v = red[bb][lane + off];
                    if (v > m) m = v;
                }
#pragma unroll
                for (int off = 16; off; off >>= 1) {
                    u64 v = __shfl_down_sync(0xffffffffu, m, off);
                    if (v > m) m = v;
                }
                if (lane == 0) atomicMax(&g_amax[step][b0 + bb], m);
            }
        }
        // --- arrive ---
        __syncthreads();
        if (tid == 0) {
            __threadfence();                   // release
            atomicAdd(&g_done[group][step], 1u);
        }
    }
}

// ---------------- launch ----------------
extern "C" void kernel_launch(void* const* d_in, const int* in_sizes, int n_in,
                              void* d_out, int out_size) {
    const int*   en_batch = (const int*)d_in[0];
    const int*   en_lens  = (const int*)d_in[1];
    const int*   de_batch = (const int*)d_in[2];
    const float* en_emb   = (const float*)d_in[3];
    const float* enc_Wih  = (const float*)d_in[4];
    const float* enc_Whh  = (const float*)d_in[5];
    const float* enc_bih  = (const float*)d_in[6];
    const float* enc_bhh  = (const float*)d_in[7];
    const float* de_emb   = (const float*)d_in[8];
    const float* dec_Wih  = (const float*)d_in[9];
    const float* dec_Whh  = (const float*)d_in[10];
    const float* dec_bih  = (const float*)d_in[11];
    const float* dec_bhh  = (const float*)d_in[12];
    const float* fc_W     = (const float*)d_in[13];
    const float* fc_b     = (const float*)d_in[14];
    float* out = (float*)d_out;

    cudaFuncSetAttribute(seq2seq_kernel,
                         cudaFuncAttributeMaxDynamicSharedMemorySize, SMEM_TOTAL);
    seq2seq_kernel<<<NBLK, 256, SMEM_TOTAL>>>(
        en_batch, en_lens, de_batch, en_emb,
        enc_Wih, enc_Whh, enc_bih, enc_bhh,
        de_emb, dec_Wih, dec_bih, dec_bhh, dec_Whh,
        fc_W, fc_b, out);
}